// round 12
// baseline (speedup 1.0000x reference)
#include <cuda_runtime.h>
#include <cstdint>

// x: (8,16,2000,128) fp32. Per (b,c,f) column: POOL=10 block sums, causal
// cumulative mean/var over pooled blocks, normalize. Single pass.
//
// Grid = 1024 CTAs: (b*C+c) x (f-group QF=16), 128 threads. Ring NS=5 tiles
// (TB=8 blocks x 10 x 16 = 5120 B). float2-wide consume: thread
// (b = tid>>4, h = (tid>>3)&1, f2 = tid&7) owns rows [b*10+h*5, +5) of 2
// adjacent f-columns: 5 LDS.64 in, one float4 block-sum exchange, distributed
// scan via LDS.128 + ping-pong carry, 5 STG.64 streaming out. Half the
// data-movement instructions of the scalar engine; 2 barriers/tile.

#define TT      2000
#define FF      128
#define PP      10
#define TT1     200
#define TB      8                    // pooled blocks per tile
#define NT      25                   // tiles
#define NS      5                    // ring stages
#define QF      16                   // f-columns per CTA
#define ROWS    (TB * PP)            // 80 rows per tile
#define TILE_F  (ROWS * QF)          // 1280 floats
#define TILE_B  (TILE_F * 4)         // 5120 B
#define SLOTS4  (TILE_F / 4)         // 320 float4 slots
#define ROW_B   (FF * 4)             // 512 B global row stride
#define EPSV    1e-5f

__device__ __forceinline__ uint32_t s2u32(const void* p) {
    uint32_t a;
    asm("{ .reg .u64 t; cvta.to.shared.u64 t, %1; cvt.u32.u64 %0, t; }"
        : "=r"(a) : "l"(p));
    return a;
}
__device__ __forceinline__ void cp16(uint32_t saddr, const void* gaddr) {
    asm volatile("cp.async.cg.shared.global [%0], [%1], 16;\n"
                 :: "r"(saddr), "l"(gaddr));
}
#define CP_COMMIT() asm volatile("cp.async.commit_group;\n")
#define CP_WAIT(n)  asm volatile("cp.async.wait_group %0;\n" :: "n"(n))

__global__ void __launch_bounds__(128)
inorm_kernel(const float* __restrict__ x, float* __restrict__ out)
{
    __shared__ float  ring[NS * TILE_F];        // 25600 B
    __shared__ float4 bsArr[TB * 2 * 8];        //  2048 B  [(b,h)][f2]
    __shared__ float4 carry[2][8];              //   256 B

    const int col = blockIdx.x >> 3;            // 0..127
    const int q   = blockIdx.x & 7;             // f-group of 16
    const int tid = threadIdx.x;
    const int b   = tid >> 4;                   // block within tile, 0..7
    const int h   = (tid >> 3) & 1;             // half of block (rows 0-4/5-9)
    const int f2  = tid & 7;                    // float2 column within group

    const char* gq = (const char*)(x   + (size_t)col * (TT * FF) + q * QF);
    char*       oq = (char*)(out + (size_t)col * (TT * FF) + q * QF);

    const uint32_t sring = s2u32(ring);

    if (tid < 8)
        carry[0][tid] = make_float4(0.f, 0.f, 0.f, 0.f);

    // Prologue: fill ring with tiles 0..NS-1 (one commit group per stage)
    #pragma unroll
    for (int st = 0; st < NS; st++) {
        #pragma unroll
        for (int i = 0; i < 3; i++) {
            const int j = tid + 128 * i;        // float4 slot, guard at 320
            if (j < SLOTS4) {
                const int r  = j >> 2;
                const int c4 = j & 3;
                cp16(sring + st * TILE_B + j * 16,
                     gq + (size_t)(st * ROWS + r) * ROW_B + c4 * 16);
            }
        }
        CP_COMMIT();
    }

    int st = 0;

    #pragma unroll 1
    for (int t = 0; t < NT; t++) {
        CP_WAIT(NS - 1);
        __syncthreads();          // stage st ready; carry[t&1] published

        const float* tile = ring + st * TILE_F;

        // ── A: load my 5 rows x 2 f-columns once into registers (LDS.64)
        float2 a[5];
        {
            const float2* rp = (const float2*)(tile + (b * PP + h * 5) * QF) + f2;
            #pragma unroll
            for (int i = 0; i < 5; i++) a[i] = rp[i * (QF / 2)];
        }
        float bs0 = 0.f, bq0 = 0.f, bs1 = 0.f, bq1 = 0.f;
        #pragma unroll
        for (int i = 0; i < 5; i++) {
            bs0 += a[i].x; bq0 = fmaf(a[i].x, a[i].x, bq0);
            bs1 += a[i].y; bq1 = fmaf(a[i].y, a[i].y, bq1);
        }
        bsArr[(b * 2 + h) * 8 + f2] = make_float4(bs0, bq0, bs1, bq1);
        __syncthreads();          // bsArr ready; stage st consumed to regs

        // ── B: distributed scan over blocks 0..b (both halves) + carry
        float s0, q0, s1, q1;
        {
            const float4 c0 = carry[t & 1][f2];
            s0 = c0.x; q0 = c0.y; s1 = c0.z; q1 = c0.w;
            #pragma unroll
            for (int j = 0; j < TB; j++) {
                if (j <= b) {                  // uniform per (b); LDS.128
                    const float4 v0 = bsArr[(j * 2 + 0) * 8 + f2];
                    const float4 v1 = bsArr[(j * 2 + 1) * 8 + f2];
                    s0 += v0.x + v1.x; q0 += v0.y + v1.y;
                    s1 += v0.z + v1.z; q1 += v0.w + v1.w;
                }
            }
            if (b == TB - 1 && h == 1)         // tid 120..127 publish carry
                carry[(t + 1) & 1][f2] = make_float4(s0, q0, s1, q1);
        }
        const float invn = __fdividef(1.0f, (float)((t * TB + b + 1) * PP));
        const float m0   = s0 * invn;
        const float m1   = s1 * invn;
        const float r0   = rsqrtf(fmaf(-m0, m0, q0 * invn) + EPSV);
        const float r1   = rsqrtf(fmaf(-m1, m1, q1 * invn) + EPSV);

        // ── C: normalize from registers, streaming STG.64
        {
            char* og = oq + (size_t)(t * ROWS + b * PP + h * 5) * ROW_B + f2 * 8;
            #pragma unroll
            for (int i = 0; i < 5; i++)
                __stcs((float2*)(og + (size_t)i * ROW_B),
                       make_float2((a[i].x - m0) * r0, (a[i].y - m1) * r1));
        }

        // ── refill stage st with tile t+NS (all warps; always commit)
        const int tn = t + NS;
        if (tn < NT) {
            #pragma unroll
            for (int i = 0; i < 3; i++) {
                const int j = tid + 128 * i;
                if (j < SLOTS4) {
                    const int r2 = j >> 2;
                    const int c4 = j & 3;
                    cp16(sring + st * TILE_B + j * 16,
                         gq + (size_t)(tn * ROWS + r2) * ROW_B + c4 * 16);
                }
            }
        }
        CP_COMMIT();

        if (++st == NS) st = 0;
    }
}

extern "C" void kernel_launch(void* const* d_in, const int* in_sizes, int n_in,
                              void* d_out, int out_size)
{
    const float* x   = (const float*)d_in[0];
    float*       out = (float*)d_out;
    inorm_kernel<<<1024, 128>>>(x, out);
}

// round 14
// speedup vs baseline: 1.0419x; 1.0419x over previous
#include <cuda_runtime.h>
#include <cstdint>

// x: (8,16,2000,128) fp32. Per (b,c,f) column: POOL=10 block sums, causal
// cumulative mean/var over pooled blocks, normalize. Single pass.
//
// Grid = 1024 CTAs: (b*C+c) x (f-group QF=16), 128 threads, ring NS=5 tiles
// (5120 B each), register consume + distributed scan (R11 engine, bench 47.6).
// R14: bank-conflict-free phase A/C. Block stride 160 floats ≡ 0 mod 32 banks,
// so in R11 the two half-warps (blocks 2w, 2w+1) collided on every LDS.
// Fix: row visit order i = (k + rp) % PP, rp = b&1. The two permutations have
// opposite row parity at every step k (incl. the 9->0 wrap), giving disjoint
// bank sets {f} / {16+f}. Register index stays the constant k (sum is
// commutative); only addresses use i, in both the LDS and the matching STG.

#define TT      2000
#define FF      128
#define PP      10
#define TT1     200
#define TB      8                    // pooled blocks per tile
#define NT      25                   // tiles
#define NS      5                    // ring stages
#define QF      16                   // f-columns per CTA
#define ROWS    (TB * PP)            // 80 rows per tile
#define TILE_F  (ROWS * QF)          // 1280 floats
#define TILE_B  (TILE_F * 4)         // 5120 B
#define SLOTS4  (TILE_F / 4)         // 320 float4 slots
#define ROW_B   (FF * 4)             // 512 B global row stride
#define EPSV    1e-5f

__device__ __forceinline__ uint32_t s2u32(const void* p) {
    uint32_t a;
    asm("{ .reg .u64 t; cvta.to.shared.u64 t, %1; cvt.u32.u64 %0, t; }"
        : "=r"(a) : "l"(p));
    return a;
}
__device__ __forceinline__ void cp16(uint32_t saddr, const void* gaddr) {
    asm volatile("cp.async.cg.shared.global [%0], [%1], 16;\n"
                 :: "r"(saddr), "l"(gaddr));
}
#define CP_COMMIT() asm volatile("cp.async.commit_group;\n")
#define CP_WAIT(n)  asm volatile("cp.async.wait_group %0;\n" :: "n"(n))

__global__ void __launch_bounds__(128)
inorm_kernel(const float* __restrict__ x, float* __restrict__ out)
{
    __shared__ float  ring[NS * TILE_F];        // 25600 B
    __shared__ float2 bsArr[TB * QF];           //  1024 B
    __shared__ float2 carry[2][QF];             //   256 B

    const int col = blockIdx.x >> 3;            // 0..127
    const int q   = blockIdx.x & 7;             // f-group of 16
    const int tid = threadIdx.x;
    const int b   = tid >> 4;                   // block within tile, 0..7
    const int f   = tid & 15;                   // f within group
    const int rp  = b & 1;                      // row-order phase (parity fix)

    const char* gq = (const char*)(x   + (size_t)col * (TT * FF) + q * QF);
    char*       oq = (char*)(out + (size_t)col * (TT * FF) + q * QF);

    const uint32_t sring = s2u32(ring);

    if (tid < QF)
        carry[0][tid] = make_float2(0.f, 0.f);

    // Prologue: fill ring with tiles 0..NS-1 (one commit group per stage)
    #pragma unroll
    for (int st = 0; st < NS; st++) {
        #pragma unroll
        for (int i = 0; i < 3; i++) {
            const int j = tid + 128 * i;        // float4 slot, guard at 320
            if (j < SLOTS4) {
                const int r  = j >> 2;
                const int c4 = j & 3;
                cp16(sring + st * TILE_B + j * 16,
                     gq + (size_t)(st * ROWS + r) * ROW_B + c4 * 16);
            }
        }
        CP_COMMIT();
    }

    int st = 0;

    #pragma unroll 1
    for (int t = 0; t < NT; t++) {
        CP_WAIT(NS - 1);
        __syncthreads();          // stage st ready; carry[t&1] published

        const float* tile = ring + st * TILE_F;

        // ── A: load my block's 10 rows once into registers, visiting rows in
        // order i = (k + rp) % PP so the two half-warps touch opposite-parity
        // rows at each step k -> disjoint bank sets, zero conflicts.
        float a[PP];
        {
            const float* base = tile + b * (PP * QF) + f;
            #pragma unroll
            for (int k = 0; k < PP; k++) {
                int i = k + rp; if (i == PP) i = 0;   // (k+rp)%PP, rp∈{0,1}
                a[k] = base[i * QF];
            }
        }
        float bs = 0.f, bs2 = 0.f;
        #pragma unroll
        for (int k = 0; k < PP; k++) { bs += a[k]; bs2 = fmaf(a[k], a[k], bs2); }
        bsArr[b * QF + f] = make_float2(bs, bs2);
        __syncthreads();          // bsArr ready; stage st consumed to regs

        // ── B: distributed scan. thread (b,f) sums bsArr[0..b] + carry.
        float sA, s2A;
        {
            const float2 c0 = carry[t & 1][f];
            sA = c0.x; s2A = c0.y;
            #pragma unroll
            for (int j = 0; j < TB; j++) {
                if (j <= b) {
                    const float2 v = bsArr[j * QF + f];
                    sA += v.x; s2A += v.y;
                }
            }
            if (b == TB - 1)
                carry[(t + 1) & 1][f] = make_float2(sA, s2A);
        }
        const float invn = __fdividef(1.0f, (float)((t * TB + b + 1) * PP));
        const float m    = sA * invn;
        const float var  = fmaf(-m, m, s2A * invn);
        const float r    = rsqrtf(var + EPSV);

        // ── C: normalize from registers; store a[k] back to ITS row i.
        {
            char* og = oq + (size_t)(t * ROWS + b * PP) * ROW_B + f * 4;
            #pragma unroll
            for (int k = 0; k < PP; k++) {
                int i = k + rp; if (i == PP) i = 0;
                __stcs((float*)(og + (size_t)i * ROW_B), (a[k] - m) * r);
            }
        }

        // ── refill stage st with tile t+NS (all warps; always commit)
        const int tn = t + NS;
        if (tn < NT) {
            #pragma unroll
            for (int i = 0; i < 3; i++) {
                const int j = tid + 128 * i;
                if (j < SLOTS4) {
                    const int r2 = j >> 2;
                    const int c4 = j & 3;
                    cp16(sring + st * TILE_B + j * 16,
                         gq + (size_t)(tn * ROWS + r2) * ROW_B + c4 * 16);
                }
            }
        }
        CP_COMMIT();

        if (++st == NS) st = 0;
    }
}

extern "C" void kernel_launch(void* const* d_in, const int* in_sizes, int n_in,
                              void* d_out, int out_size)
{
    const float* x   = (const float*)d_in[0];
    float*       out = (float*)d_out;
    inorm_kernel<<<1024, 128>>>(x, out);
}

// round 15
// speedup vs baseline: 1.0721x; 1.0290x over previous
#include <cuda_runtime.h>
#include <cuda.h>
#include <cstdint>

// x: (8,16,2000,128) fp32. Per (b,c,f) column: POOL=10 block sums, causal
// cumulative mean/var over pooled blocks, normalize. Single pass.
//
// Grid = 1024 CTAs: (b*C+c) x (f-group QF=16), 128 threads. Ring NS=5 tiles.
// R15: each 5120B stage (80 rows x 64B, stride 512B) is loaded with ONE
// cp.async.bulk.tensor.2d (TMA) instead of 320 cp.asyncs — kills the
// LDGSTS issue bottleneck (80 ops/warp/stage) that left DRAM 32% idle.
// Tensor map encoded host-side via cudaGetDriverEntryPoint (no -lcuda),
// passed __grid_constant__. Consume engine = R14: parity bank-conflict-free
// register loads, distributed scan w/ ping-pong carry, __stcs stores.

#define TT      2000
#define FF      128
#define PP      10
#define TT1     200
#define TB      8                    // pooled blocks per tile
#define NT      25                   // tiles
#define NS      5                    // ring stages
#define QF      16                   // f-columns per CTA
#define ROWS    (TB * PP)            // 80 rows per tile
#define TILE_F  (ROWS * QF)          // 1280 floats
#define TILE_B  (TILE_F * 4)         // 5120 B
#define ROW_B   (FF * 4)             // 512 B global row stride
#define EPSV    1e-5f

__device__ __forceinline__ uint32_t s2u32(const void* p) {
    uint32_t a;
    asm("{ .reg .u64 t; cvta.to.shared.u64 t, %1; cvt.u32.u64 %0, t; }"
        : "=r"(a) : "l"(p));
    return a;
}
__device__ __forceinline__ void mbar_init(uint32_t m, uint32_t cnt) {
    asm volatile("mbarrier.init.shared.b64 [%0], %1;" :: "r"(m), "r"(cnt) : "memory");
}
__device__ __forceinline__ void mbar_expect_tx(uint32_t m, uint32_t bytes) {
    asm volatile("mbarrier.arrive.expect_tx.shared.b64 _, [%0], %1;"
                 :: "r"(m), "r"(bytes) : "memory");
}
__device__ __forceinline__ void mbar_wait(uint32_t m, uint32_t ph) {
    uint32_t done;
    asm volatile(
        "{\n\t.reg .pred p;\n\t"
        "mbarrier.try_wait.parity.acquire.cta.shared::cta.b64 p, [%1], %2;\n\t"
        "selp.b32 %0, 1, 0, p;\n\t}"
        : "=r"(done) : "r"(m), "r"(ph) : "memory");
    if (!done) {
        asm volatile(
            "{\n\t.reg .pred P1;\n\t"
            "W_%=:\n\t"
            "mbarrier.try_wait.parity.acquire.cta.shared::cta.b64 P1, [%0], %1, 0x989680;\n\t"
            "@P1 bra.uni D_%=;\n\t"
            "bra.uni W_%=;\n\t"
            "D_%=:\n\t}"
            :: "r"(m), "r"(ph) : "memory");
    }
}
__device__ __forceinline__ void tma_load_2d(uint32_t sdst, const void* tmap,
                                            int c0, int c1, uint32_t mbar) {
    asm volatile(
        "cp.async.bulk.tensor.2d.shared::cta.global.tile.mbarrier::complete_tx::bytes "
        "[%0], [%1, {%2, %3}], [%4];"
        :: "r"(sdst), "l"(tmap), "r"(c0), "r"(c1), "r"(mbar) : "memory");
}

__global__ void __launch_bounds__(128)
inorm_kernel(const __grid_constant__ CUtensorMap tmap, float* __restrict__ out)
{
    __shared__ alignas(128) float ring[NS * TILE_F];   // 25600 B
    __shared__ float2 bsArr[TB * QF];                  //  1024 B
    __shared__ float2 carry[2][QF];                    //   256 B
    __shared__ alignas(8) uint64_t mbarMem[NS];

    const int col = blockIdx.x >> 3;            // 0..127
    const int q   = blockIdx.x & 7;             // f-group of 16
    const int tid = threadIdx.x;
    const int b   = tid >> 4;                   // block within tile, 0..7
    const int f   = tid & 15;                   // f within group
    const int rp  = b & 1;                      // row-order parity (bank fix)

    const int c0    = q * QF;                   // inner coord (elements)
    const int rbase = col * TT;                 // row base for this column

    char* oq = (char*)(out + (size_t)col * (TT * FF) + q * QF);

    const uint32_t sring = s2u32(ring);
    const uint32_t mb    = s2u32(mbarMem);
    #define FULLB(s) (mb + (s) * 8)

    if (tid == 0) {
        #pragma unroll
        for (int s = 0; s < NS; s++) mbar_init(FULLB(s), 1);
    }
    if (tid < QF)
        carry[0][tid] = make_float2(0.f, 0.f);
    __syncthreads();
    asm volatile("fence.proxy.async.shared::cta;" ::: "memory");

    // Prologue: one TMA per stage for tiles 0..NS-1
    if (tid == 0) {
        #pragma unroll
        for (int s = 0; s < NS; s++) {
            mbar_expect_tx(FULLB(s), TILE_B);
            tma_load_2d(sring + s * TILE_B, &tmap, c0, rbase + s * ROWS, FULLB(s));
        }
    }

    int st = 0, ph = 0;

    #pragma unroll 1
    for (int t = 0; t < NT; t++) {
        mbar_wait(FULLB(st), ph);
        __syncthreads();          // all threads past wait; prev-iter bsArr
                                  // reads finished -> safe to rewrite bsArr

        const float* tile = ring + st * TILE_F;

        // ── A: load my block's 10 rows once into registers, row order
        // i = (k+rp)%PP so half-warps touch opposite-parity rows (disjoint
        // bank sets {f}/{16+f}); register index stays constant k.
        float a[PP];
        {
            const float* base = tile + b * (PP * QF) + f;
            #pragma unroll
            for (int k = 0; k < PP; k++) {
                int i = k + rp; if (i == PP) i = 0;
                a[k] = base[i * QF];
            }
        }
        float bs = 0.f, bs2 = 0.f;
        #pragma unroll
        for (int k = 0; k < PP; k++) { bs += a[k]; bs2 = fmaf(a[k], a[k], bs2); }
        bsArr[b * QF + f] = make_float2(bs, bs2);
        __syncthreads();          // bsArr ready; ALL tile reads done

        // ── refill stage st with tile t+NS (tile fully consumed to regs)
        if (tid == 0) {
            const int tn = t + NS;
            if (tn < NT) {
                mbar_expect_tx(FULLB(st), TILE_B);
                tma_load_2d(sring + st * TILE_B, &tmap, c0,
                            rbase + tn * ROWS, FULLB(st));
            }
        }

        // ── B: distributed scan. thread (b,f) sums bsArr[0..b] + carry.
        float sA, s2A;
        {
            const float2 cc = carry[t & 1][f];
            sA = cc.x; s2A = cc.y;
            #pragma unroll
            for (int j = 0; j < TB; j++) {
                if (j <= b) {
                    const float2 v = bsArr[j * QF + f];
                    sA += v.x; s2A += v.y;
                }
            }
            if (b == TB - 1)
                carry[(t + 1) & 1][f] = make_float2(sA, s2A);
        }
        const float invn = __fdividef(1.0f, (float)((t * TB + b + 1) * PP));
        const float m    = sA * invn;
        const float var  = fmaf(-m, m, s2A * invn);
        const float r    = rsqrtf(var + EPSV);

        // ── C: normalize from registers; a[k] goes back to ITS row i.
        {
            char* og = oq + (size_t)(t * ROWS + b * PP) * ROW_B + f * 4;
            #pragma unroll
            for (int k = 0; k < PP; k++) {
                int i = k + rp; if (i == PP) i = 0;
                __stcs((float*)(og + (size_t)i * ROW_B), (a[k] - m) * r);
            }
        }

        if (++st == NS) { st = 0; ph ^= 1; }
    }
}

typedef CUresult (*pfn_encode_t)(
    CUtensorMap*, CUtensorMapDataType, cuuint32_t, void*,
    const cuuint64_t*, const cuuint64_t*, const cuuint32_t*, const cuuint32_t*,
    CUtensorMapInterleave, CUtensorMapSwizzle, CUtensorMapL2promotion,
    CUtensorMapFloatOOBfill);

extern "C" void kernel_launch(void* const* d_in, const int* in_sizes, int n_in,
                              void* d_out, int out_size)
{
    const float* x   = (const float*)d_in[0];
    float*       out = (float*)d_out;

    // Fetch cuTensorMapEncodeTiled through cudart (no -lcuda needed).
    pfn_encode_t encode = nullptr;
    cudaDriverEntryPointQueryResult qr;
    cudaGetDriverEntryPoint("cuTensorMapEncodeTiled", (void**)&encode,
                            cudaEnableDefault, &qr);

    // x viewed as 2D: inner = 128 floats (F), rows = 128 cols * 2000 t.
    CUtensorMap tmap;
    cuuint64_t dims[2]    = { (cuuint64_t)FF, (cuuint64_t)(128 * TT) };
    cuuint64_t strides[1] = { (cuuint64_t)ROW_B };
    cuuint32_t box[2]     = { QF, ROWS };          // 16 floats x 80 rows
    cuuint32_t estr[2]    = { 1, 1 };
    encode(&tmap, CU_TENSOR_MAP_DATA_TYPE_FLOAT32, 2, (void*)x,
           dims, strides, box, estr,
           CU_TENSOR_MAP_INTERLEAVE_NONE, CU_TENSOR_MAP_SWIZZLE_NONE,
           CU_TENSOR_MAP_L2_PROMOTION_L2_128B, CU_TENSOR_MAP_FLOAT_OOB_FILL_NONE);

    inorm_kernel<<<1024, 128>>>(tmap, out);
}